// round 8
// baseline (speedup 1.0000x reference)
#include <cuda_runtime.h>
#include <cuda_fp16.h>
#include <cuda_bf16.h>
#include <cstdint>

#define BATCH      32
#define W_DIM      512
#define CHANNELS   1024
#define GRID_HW    64
#define HW         (GRID_HW * GRID_HW)      // 4096
#define TWO_PI     6.28318530717958647692f
#define GAIN       0.044194173824159216f    // 1/sqrt(512)
#define WSCALE     0.03125f                 // 1/sqrt(1024)

// ---------------- scratch (device globals; no runtime alloc) -----------------
__device__ float  g_frx[BATCH * CHANNELS];
__device__ float  g_fry[BATCH * CHANNELS];
__device__ float  g_ph [BATCH * CHANNELS];
__device__ float  g_amp[BATCH * CHANNELS];

// fp16 trig tables, c-FASTEST: [b][p][c]
__device__ __half g_SAh[BATCH * GRID_HW * CHANNELS];  // amp*sin(2pi g(w) frx)
__device__ __half g_CAh[BATCH * GRID_HW * CHANNELS];  // amp*cos(2pi g(w) frx)
__device__ __half g_SBh[BATCH * GRID_HW * CHANNELS];  // sin(2pi (g(h) fry + ph))
__device__ __half g_CBh[BATCH * GRID_HW * CHANNELS];  // cos(2pi (g(h) fry + ph))

// fp16 feature tensor F[b][px=h*64+w][c]  (256 MB)
__device__ __half g_F[(size_t)BATCH * HW * CHANNELS];

// fp16 weight (1/sqrt(C) folded), row-major [o][c]
__device__ __half g_Wh[CHANNELS * CHANNELS];

// ---------------- PTX helpers -----------------------------------------------
__device__ __forceinline__ uint32_t smem_u32(const void* p) {
    uint32_t a;
    asm("{ .reg .u64 t; cvta.to.shared.u64 t, %1; cvt.u32.u64 %0, t; }"
        : "=r"(a) : "l"(p));
    return a;
}

__device__ __forceinline__ void ldsm4(uint32_t* r, uint32_t addr) {
    asm volatile("ldmatrix.sync.aligned.m8n8.x4.shared.b16 {%0,%1,%2,%3}, [%4];"
                 : "=r"(r[0]), "=r"(r[1]), "=r"(r[2]), "=r"(r[3]) : "r"(addr));
}

__device__ __forceinline__ void mma16816(float* d, const uint32_t* a,
                                         const uint32_t* b) {
    asm volatile(
        "mma.sync.aligned.m16n8k16.row.col.f32.f16.f16.f32 "
        "{%0,%1,%2,%3}, {%4,%5,%6,%7}, {%8,%9}, {%0,%1,%2,%3};"
        : "+f"(d[0]), "+f"(d[1]), "+f"(d[2]), "+f"(d[3])
        : "r"(a[0]), "r"(a[1]), "r"(a[2]), "r"(a[3]), "r"(b[0]), "r"(b[1]));
}

__device__ __forceinline__ void cp16(uint32_t dst, const void* src) {
    asm volatile("cp.async.ca.shared.global [%0], [%1], 16;"
                 :: "r"(dst), "l"(src));
}
#define CP_COMMIT() asm volatile("cp.async.commit_group;" ::: "memory")
#define CP_WAIT0()  asm volatile("cp.async.wait_group 0;"  ::: "memory")
#define CP_WAIT1()  asm volatile("cp.async.wait_group 1;"  ::: "memory")

// ---------------- stage 1: per-batch params ----------------------------------
__global__ void params_kernel(const float* __restrict__ w,
                              const float* __restrict__ affine_w,
                              const float* __restrict__ affine_b,
                              const float* __restrict__ freqs,
                              const float* __restrict__ phases) {
    __shared__ float t[BATCH][4];
    __shared__ float cs[BATCH], ss[BATCH], trx[BATCH], trY[BATCH];

    int tid = threadIdx.x;          // 128 threads
    int b = tid >> 2, j = tid & 3;

    float acc = 0.f;
    const float* wr = w + b * W_DIM;
    const float* ar = affine_w + j * W_DIM;
    #pragma unroll 4
    for (int k = 0; k < W_DIM; k++) acc += wr[k] * ar[k];
    t[b][j] = acc * GAIN + affine_b[j];
    __syncthreads();

    if (j == 0) {
        float t0 = t[b][0], t1 = t[b][1], t2 = t[b][2], t3 = t[b][3];
        float inv = rsqrtf(t0 * t0 + t1 * t1);
        float c = t0 * inv, s = t1 * inv, tx = t2 * inv, ty = t3 * inv;
        cs[b] = c; ss[b] = s;
        trx[b] = -c * tx + s * ty;
        trY[b] = -s * tx - c * ty;
    }
    __syncthreads();

    for (int idx = tid; idx < BATCH * CHANNELS; idx += 128) {
        int bb = idx >> 10, c = idx & (CHANNELS - 1);
        float f0 = freqs[c * 2], f1 = freqs[c * 2 + 1];
        float C = cs[bb], S = ss[bb];
        float frx = f0 * C + f1 * S;
        float fry = -f0 * S + f1 * C;
        float ph  = phases[c] + f0 * trx[bb] + f1 * trY[bb];
        float nrm = sqrtf(frx * frx + fry * fry);
        float amp = 1.0f - (nrm - 2.0f) * (1.0f / 30.0f);
        amp = fminf(fmaxf(amp, 0.0f), 1.0f);
        g_frx[idx] = frx; g_fry[idx] = fry; g_ph[idx] = ph; g_amp[idx] = amp;
    }
}

// ---------------- stage 1b: weight -> fp16 -----------------------------------
__global__ void wconv_kernel(const float* __restrict__ weight) {
    int idx = blockIdx.x * blockDim.x + threadIdx.x;
    for (int i = idx; i < CHANNELS * CHANNELS; i += gridDim.x * blockDim.x)
        g_Wh[i] = __float2half(weight[i] * WSCALE);
}

// ---------------- stage 2: fp16 trig tables (c-fastest) ----------------------
__global__ void tables_kernel() {
    int p = blockIdx.x, b = blockIdx.y;
    float g = ((2 * p + 1) * (1.0f / GRID_HW) - 1.0f) * 0.5f;
    int o = (b * GRID_HW + p) * CHANNELS;
    int base = b * CHANNELS;
    for (int c = threadIdx.x; c < CHANNELS; c += blockDim.x) {
        float frx = g_frx[base + c], fry = g_fry[base + c];
        float ph = g_ph[base + c], amp = g_amp[base + c];
        float sa, ca, sb, cb;
        sincosf(TWO_PI * g * frx, &sa, &ca);
        sincosf(TWO_PI * (g * fry + ph), &sb, &cb);
        g_SAh[o + c] = __float2half(amp * sa);
        g_CAh[o + c] = __float2half(amp * ca);
        g_SBh[o + c] = __float2half(sb);
        g_CBh[o + c] = __float2half(cb);
    }
}

// ---------------- stage 3: materialize F (fp16, coalesced) -------------------
// F[b][h*64+w][c] = SA[b,w,c]*CB[b,h,c] + CA[b,w,c]*SB[b,h,c]
__global__ void __launch_bounds__(256)
features_kernel() {
    __shared__ __half sSB[CHANNELS], sCB[CHANNELS];
    int h = blockIdx.x, b = blockIdx.y;
    int tid = threadIdx.x;

    // load SB/CB rows for (b,h): 128 uint4 each
    {
        int rb = (b * GRID_HW + h) * CHANNELS;
        if (tid < 128)
            *(uint4*)&sSB[tid * 8] = *(const uint4*)&g_SBh[rb + tid * 8];
        else
            *(uint4*)&sCB[(tid - 128) * 8] = *(const uint4*)&g_CBh[rb + (tid - 128) * 8];
    }
    __syncthreads();

    int w2 = tid >> 7;              // 0..1
    int c8 = (tid & 127) * 8;       // c offset
    uint4 xsb = *(const uint4*)&sSB[c8];
    uint4 xcb = *(const uint4*)&sCB[c8];

    size_t fb = ((size_t)(b * HW + h * GRID_HW) << 10) + c8;
    int ab = (b * GRID_HW) << 10;

    #pragma unroll 4
    for (int wp = 0; wp < GRID_HW; wp += 2) {
        int w = wp + w2;
        uint4 xsa = *(const uint4*)&g_SAh[ab + (w << 10) + c8];
        uint4 xca = *(const uint4*)&g_CAh[ab + (w << 10) + c8];
        uint4 o;
        #pragma unroll
        for (int j = 0; j < 4; j++)
            ((__half2*)&o)[j] = __hfma2(((const __half2*)&xsa)[j], ((const __half2*)&xcb)[j],
                                __hmul2(((const __half2*)&xca)[j], ((const __half2*)&xsb)[j]));
        *(uint4*)&g_F[fb + ((size_t)w << 10)] = o;
    }
}

// ---------------- stage 4: cp.async mma.sync GEMM ----------------------------
// CTA tile: M=128 (o) x N=128 (px), K=1024 in 16 iters of BK=64.
// 4 warps of 64x64 (2m x 2n). 3-stage cp.async pipeline. 2 CTAs/SM.
#define BK       64
#define NKIT     (CHANNELS / BK)   // 16
#define STR      72                // halves per row (64 + 8 pad)
#define TILEH    (128 * STR)       // 9216 halves per operand tile
#define STAGEH   (2 * TILEH)       // 18432 halves per stage (A then B)
#define SMEM_BYTES (3 * STAGEH * 2)   // 110592

__global__ void __launch_bounds__(128, 2)
gemm_mma(float* __restrict__ out) {
    extern __shared__ __half sh[];
    int tid = threadIdx.x;
    int ot = blockIdx.x;   // 8
    int pt = blockIdx.y;   // 32
    int b  = blockIdx.z;   // 32

    uint32_t su = smem_u32(sh);

    // ---- staging map: 8 lanes/row, 16 row-groups of 8 -----------------------
    int r = tid >> 3, seg = tid & 7;
    const __half* wsrc = g_Wh + (size_t)(ot * 128 + r) * CHANNELS + seg * 8;
    const __half* fsrc = g_F + ((size_t)(b * HW + pt * 128 + r) << 10) + seg * 8;

    auto stage = [&](int k, int buf) {
        uint32_t ab = su + (uint32_t)(buf * STAGEH + r * STR + seg * 8) * 2;
        uint32_t bb = ab + (uint32_t)TILEH * 2;
        const __half* wk = wsrc + k * BK;
        const __half* fk = fsrc + k * BK;
        #pragma unroll
        for (int j = 0; j < 8; j++) {
            cp16(ab + (uint32_t)(j * 16 * STR) * 2, wk + (size_t)(j * 16) * CHANNELS);
            cp16(bb + (uint32_t)(j * 16 * STR) * 2, fk + (size_t)(j * 16) * CHANNELS);
        }
    };

    // ---- mma geometry: 4 warps, 2m x 2n, 64x64 each -------------------------
    int wid = tid >> 5, lane = tid & 31;
    int m0 = (wid >> 1) * 64;
    int n0 = (wid & 1) * 64;
    int la = lane & 7, lb = (lane >> 3) & 1, lc = lane >> 4;
    uint32_t aOff = (uint32_t)((m0 + la + lb * 8) * STR + lc * 8) * 2;
    uint32_t bOff = (uint32_t)((n0 + la + lc * 8) * STR + lb * 8) * 2 + (uint32_t)TILEH * 2;

    float acc[4][8][4];
    #pragma unroll
    for (int i = 0; i < 4; i++)
        #pragma unroll
        for (int j = 0; j < 8; j++)
            #pragma unroll
            for (int q = 0; q < 4; q++) acc[i][j][q] = 0.f;

    // ---- prologue: stage 0,1 ------------------------------------------------
    stage(0, 0); CP_COMMIT();
    stage(1, 1); CP_COMMIT();

    // ---- main loop: 3-stage pipeline ----------------------------------------
    #pragma unroll 1
    for (int k = 0; k < NKIT; k++) {
        CP_WAIT1();            // group k complete (k+1 may still fly)
        __syncthreads();       // all warps past MMA(k-1); buf (k+2)%3 free

        if (k + 2 < NKIT) stage(k + 2, (k + 2) % 3);
        CP_COMMIT();

        uint32_t aA = su + (uint32_t)((k % 3) * STAGEH) * 2 + aOff;
        uint32_t bA = su + (uint32_t)((k % 3) * STAGEH) * 2 + bOff;
        #pragma unroll
        for (int ks = 0; ks < 4; ks++) {
            uint32_t af[4][4], bf[4][4];
            #pragma unroll
            for (int im = 0; im < 4; im++)
                ldsm4(af[im], aA + (uint32_t)(im * 16 * STR) * 2 + ks * 32);
            #pragma unroll
            for (int in = 0; in < 4; in++)
                ldsm4(bf[in], bA + (uint32_t)(in * 16 * STR) * 2 + ks * 32);
            #pragma unroll
            for (int im = 0; im < 4; im++)
                #pragma unroll
                for (int in = 0; in < 4; in++) {
                    mma16816(acc[im][2 * in],     af[im], &bf[in][0]);
                    mma16816(acc[im][2 * in + 1], af[im], &bf[in][2]);
                }
        }
    }

    // ---- epilogue: direct STG, 32B-sector coalesced -------------------------
    #pragma unroll
    for (int im = 0; im < 4; im++) {
        int o = ot * 128 + m0 + im * 16 + (lane >> 2);
        float* p = out + ((size_t)(b * CHANNELS + o)) * HW
                       + (size_t)pt * 128 + n0 + 2 * (lane & 3);
        #pragma unroll
        for (int inf = 0; inf < 8; inf++) {
            float2 vlo = make_float2(acc[im][inf][0], acc[im][inf][1]);
            float2 vhi = make_float2(acc[im][inf][2], acc[im][inf][3]);
            *(float2*)(p + inf * 8)          = vlo;   // row o
            *(float2*)(p + inf * 8 + 8 * HW) = vhi;   // row o+8
        }
    }
}

// ---------------- launch ------------------------------------------------------
extern "C" void kernel_launch(void* const* d_in, const int* in_sizes, int n_in,
                              void* d_out, int out_size) {
    const float* w        = (const float*)d_in[0];
    const float* affine_w = (const float*)d_in[1];
    const float* affine_b = (const float*)d_in[2];
    const float* freqs    = (const float*)d_in[3];
    const float* phases   = (const float*)d_in[4];
    const float* weight   = (const float*)d_in[5];
    float* out = (float*)d_out;

    cudaFuncSetAttribute(gemm_mma, cudaFuncAttributeMaxDynamicSharedMemorySize,
                         SMEM_BYTES);

    params_kernel<<<1, 128>>>(w, affine_w, affine_b, freqs, phases);
    wconv_kernel<<<512, 256>>>(weight);
    tables_kernel<<<dim3(GRID_HW, BATCH), 256>>>();
    features_kernel<<<dim3(GRID_HW, BATCH), 256>>>();
    gemm_mma<<<dim3(8, 32, BATCH), 128, SMEM_BYTES>>>(out);
}

// round 9
// speedup vs baseline: 1.0427x; 1.0427x over previous
#include <cuda_runtime.h>
#include <cuda_fp16.h>
#include <cuda_bf16.h>
#include <cstdint>

#define BATCH      32
#define W_DIM      512
#define CHANNELS   1024
#define GRID_HW    64
#define HW         (GRID_HW * GRID_HW)      // 4096
#define TWO_PI     6.28318530717958647692f
#define GAIN       0.044194173824159216f    // 1/sqrt(512)
#define WSCALE     0.03125f                 // 1/sqrt(1024)

// ---------------- scratch (device globals; no runtime alloc) -----------------
__device__ float  g_frx[BATCH * CHANNELS];
__device__ float  g_fry[BATCH * CHANNELS];
__device__ float  g_ph [BATCH * CHANNELS];

// fp16 trig tables, c-FASTEST: [b][p][c]   (amp == 1 identically; proven)
__device__ __half g_SAh[BATCH * GRID_HW * CHANNELS];  // sin(2pi g(w) frx)
__device__ __half g_CAh[BATCH * GRID_HW * CHANNELS];  // cos(2pi g(w) frx)
__device__ __half g_SBh[BATCH * GRID_HW * CHANNELS];  // sin(2pi (g(h) fry + ph))
__device__ __half g_CBh[BATCH * GRID_HW * CHANNELS];  // cos(2pi (g(h) fry + ph))

// fp16 feature tensor F[b][px=h*64+w][c]  (256 MB)
__device__ __half g_F[(size_t)BATCH * HW * CHANNELS];

// fp16 weight (1/sqrt(C) folded), row-major [o][c]
__device__ __half g_Wh[CHANNELS * CHANNELS];

// ---------------- PTX helpers -----------------------------------------------
__device__ __forceinline__ uint32_t smem_u32(const void* p) {
    uint32_t a;
    asm("{ .reg .u64 t; cvta.to.shared.u64 t, %1; cvt.u32.u64 %0, t; }"
        : "=r"(a) : "l"(p));
    return a;
}

__device__ __forceinline__ void ldsm4(uint32_t* r, uint32_t addr) {
    asm volatile("ldmatrix.sync.aligned.m8n8.x4.shared.b16 {%0,%1,%2,%3}, [%4];"
                 : "=r"(r[0]), "=r"(r[1]), "=r"(r[2]), "=r"(r[3]) : "r"(addr));
}

__device__ __forceinline__ void mma16816(float* d, const uint32_t* a,
                                         const uint32_t* b) {
    asm volatile(
        "mma.sync.aligned.m16n8k16.row.col.f32.f16.f16.f32 "
        "{%0,%1,%2,%3}, {%4,%5,%6,%7}, {%8,%9}, {%0,%1,%2,%3};"
        : "+f"(d[0]), "+f"(d[1]), "+f"(d[2]), "+f"(d[3])
        : "r"(a[0]), "r"(a[1]), "r"(a[2]), "r"(a[3]), "r"(b[0]), "r"(b[1]));
}

__device__ __forceinline__ void cp16(uint32_t dst, const void* src) {
    asm volatile("cp.async.ca.shared.global [%0], [%1], 16;"
                 :: "r"(dst), "l"(src));
}
#define CP_COMMIT() asm volatile("cp.async.commit_group;" ::: "memory")
#define CP_WAIT1()  asm volatile("cp.async.wait_group 1;"  ::: "memory")

// ---------------- stage 1: per-batch params (one block per b) ----------------
__global__ void params_kernel(const float* __restrict__ w,
                              const float* __restrict__ affine_w,
                              const float* __restrict__ affine_b,
                              const float* __restrict__ freqs,
                              const float* __restrict__ phases) {
    __shared__ float t[4];
    __shared__ float s_cs, s_ss, s_trx, s_try;

    int b = blockIdx.x;
    int tid = threadIdx.x;          // 128
    int j = tid >> 5, lane = tid & 31;

    // warp j computes t[j] = <w[b], affine_w[j]> * GAIN + affine_b[j]
    float acc = 0.f;
    const float* wr = w + b * W_DIM;
    const float* ar = affine_w + j * W_DIM;
    for (int k = lane; k < W_DIM; k += 32) acc += wr[k] * ar[k];
    #pragma unroll
    for (int s = 16; s > 0; s >>= 1)
        acc += __shfl_down_sync(0xFFFFFFFF, acc, s);
    if (lane == 0) t[j] = acc * GAIN + affine_b[j];
    __syncthreads();

    if (tid == 0) {
        float t0 = t[0], t1 = t[1], t2 = t[2], t3 = t[3];
        float inv = rsqrtf(t0 * t0 + t1 * t1);
        float c = t0 * inv, s = t1 * inv, tx = t2 * inv, ty = t3 * inv;
        s_cs = c; s_ss = s;
        s_trx = -c * tx + s * ty;
        s_try = -s * tx - c * ty;
    }
    __syncthreads();

    float C = s_cs, S = s_ss, TX = s_trx, TY = s_try;
    for (int c = tid; c < CHANNELS; c += 128) {
        float f0 = freqs[c * 2], f1 = freqs[c * 2 + 1];
        int idx = b * CHANNELS + c;
        g_frx[idx] = f0 * C + f1 * S;
        g_fry[idx] = -f0 * S + f1 * C;
        g_ph [idx] = phases[c] + f0 * TX + f1 * TY;
    }
}

// ---------------- stage 1b: weight -> fp16 -----------------------------------
__global__ void wconv_kernel(const float* __restrict__ weight) {
    int idx = blockIdx.x * blockDim.x + threadIdx.x;
    for (int i = idx; i < CHANNELS * CHANNELS; i += gridDim.x * blockDim.x)
        g_Wh[i] = __float2half(weight[i] * WSCALE);
}

// ---------------- stage 2: fp16 trig tables (c-fastest; amp==1) --------------
__global__ void tables_kernel() {
    int p = blockIdx.x, b = blockIdx.y;
    float g = ((2 * p + 1) * (1.0f / GRID_HW) - 1.0f) * 0.5f;
    int o = (b * GRID_HW + p) * CHANNELS;
    int base = b * CHANNELS;
    for (int c = threadIdx.x; c < CHANNELS; c += blockDim.x) {
        float frx = g_frx[base + c], fry = g_fry[base + c];
        float ph = g_ph[base + c];
        float sa, ca, sb, cb;
        sincosf(TWO_PI * g * frx, &sa, &ca);
        sincosf(TWO_PI * (g * fry + ph), &sb, &cb);
        g_SAh[o + c] = __float2half(sa);
        g_CAh[o + c] = __float2half(ca);
        g_SBh[o + c] = __float2half(sb);
        g_CBh[o + c] = __float2half(cb);
    }
}

// ---------------- stage 3: materialize F (fp16, coalesced) -------------------
// F[b][h*64+w][c] = SA[b,w,c]*CB[b,h,c] + CA[b,w,c]*SB[b,h,c]
__global__ void __launch_bounds__(256)
features_kernel() {
    __shared__ __half sSB[CHANNELS], sCB[CHANNELS];
    int h = blockIdx.x, b = blockIdx.y;
    int tid = threadIdx.x;

    {
        int rb = (b * GRID_HW + h) * CHANNELS;
        if (tid < 128)
            *(uint4*)&sSB[tid * 8] = *(const uint4*)&g_SBh[rb + tid * 8];
        else
            *(uint4*)&sCB[(tid - 128) * 8] = *(const uint4*)&g_CBh[rb + (tid - 128) * 8];
    }
    __syncthreads();

    int w2 = tid >> 7;              // 0..1
    int c8 = (tid & 127) * 8;
    uint4 xsb = *(const uint4*)&sSB[c8];
    uint4 xcb = *(const uint4*)&sCB[c8];

    size_t fb = ((size_t)(b * HW + h * GRID_HW) << 10) + c8;
    int ab = (b * GRID_HW) << 10;

    #pragma unroll 4
    for (int wp = 0; wp < GRID_HW; wp += 2) {
        int w = wp + w2;
        uint4 xsa = *(const uint4*)&g_SAh[ab + (w << 10) + c8];
        uint4 xca = *(const uint4*)&g_CAh[ab + (w << 10) + c8];
        uint4 o;
        #pragma unroll
        for (int j = 0; j < 4; j++)
            ((__half2*)&o)[j] = __hfma2(((const __half2*)&xsa)[j], ((const __half2*)&xcb)[j],
                                __hmul2(((const __half2*)&xca)[j], ((const __half2*)&xsb)[j]));
        *(uint4*)&g_F[fb + ((size_t)w << 10)] = o;
    }
}

// ---------------- stage 4: cp.async mma.sync GEMM ----------------------------
// CTA tile: M=128 (o) x N=128 (px), K=1024 in 16 iters of BK=64.
// 4 warps of 64x64 (2m x 2n). 3-stage cp.async pipeline. 2 CTAs/SM.
// A-fragment register double-buffering across ks; bf in-major HMMA order.
#define BK       64
#define NKIT     (CHANNELS / BK)   // 16
#define STR      72                // halves per row (64 + 8 pad)
#define TILEH    (128 * STR)       // 9216 halves per operand tile
#define STAGEH   (2 * TILEH)       // 18432 halves per stage (A then B)
#define SMEM_BYTES (3 * STAGEH * 2)   // 110592

__global__ void __launch_bounds__(128, 2)
gemm_mma(float* __restrict__ out) {
    extern __shared__ __half sh[];
    int tid = threadIdx.x;
    int ot = blockIdx.x;   // 8
    int pt = blockIdx.y;   // 32
    int b  = blockIdx.z;   // 32

    uint32_t su = smem_u32(sh);

    // ---- staging map: 8 lanes/row ------------------------------------------
    int r = tid >> 3, seg = tid & 7;
    const __half* wsrc = g_Wh + (size_t)(ot * 128 + r) * CHANNELS + seg * 8;
    const __half* fsrc = g_F + ((size_t)(b * HW + pt * 128 + r) << 10) + seg * 8;

    auto stage = [&](int k, int buf) {
        uint32_t ab = su + (uint32_t)(buf * STAGEH + r * STR + seg * 8) * 2;
        uint32_t bb = ab + (uint32_t)TILEH * 2;
        const __half* wk = wsrc + k * BK;
        const __half* fk = fsrc + k * BK;
        #pragma unroll
        for (int j = 0; j < 8; j++) {
            cp16(ab + (uint32_t)(j * 16 * STR) * 2, wk + (size_t)(j * 16) * CHANNELS);
            cp16(bb + (uint32_t)(j * 16 * STR) * 2, fk + (size_t)(j * 16) * CHANNELS);
        }
    };

    // ---- mma geometry: 4 warps, 2m x 2n, 64x64 each -------------------------
    int wid = tid >> 5, lane = tid & 31;
    int m0 = (wid >> 1) * 64;
    int n0 = (wid & 1) * 64;
    int la = lane & 7, lb = (lane >> 3) & 1, lc = lane >> 4;
    uint32_t aOff = (uint32_t)((m0 + la + lb * 8) * STR + lc * 8) * 2;
    uint32_t bOff = (uint32_t)((n0 + la + lc * 8) * STR + lb * 8) * 2 + (uint32_t)TILEH * 2;

    float acc[4][8][4];
    #pragma unroll
    for (int i = 0; i < 4; i++)
        #pragma unroll
        for (int j = 0; j < 8; j++)
            #pragma unroll
            for (int q = 0; q < 4; q++) acc[i][j][q] = 0.f;

    // ---- prologue: stage 0,1 ------------------------------------------------
    stage(0, 0); CP_COMMIT();
    stage(1, 1); CP_COMMIT();

    // ---- main loop: 3-stage pipeline, af register double-buffer -------------
    #pragma unroll 1
    for (int k = 0; k < NKIT; k++) {
        CP_WAIT1();            // group k complete (k+1 may still fly)
        __syncthreads();       // all warps past MMA(k-1); buf (k+2)%3 free

        if (k + 2 < NKIT) stage(k + 2, (k + 2) % 3);
        CP_COMMIT();

        uint32_t aA = su + (uint32_t)((k % 3) * STAGEH) * 2 + aOff;
        uint32_t bA = su + (uint32_t)((k % 3) * STAGEH) * 2 + bOff;

        uint32_t af[2][4][4];
        #pragma unroll
        for (int im = 0; im < 4; im++)
            ldsm4(af[0][im], aA + (uint32_t)(im * 16 * STR) * 2);

        #pragma unroll
        for (int ks = 0; ks < 4; ks++) {
            int cur = ks & 1;
            // bf first (consumed soonest), then prefetch af(ks+1)
            uint32_t bf[4][4];
            #pragma unroll
            for (int in = 0; in < 4; in++)
                ldsm4(bf[in], bA + (uint32_t)(in * 16 * STR) * 2 + ks * 32);
            if (ks < 3) {
                #pragma unroll
                for (int im = 0; im < 4; im++)
                    ldsm4(af[cur ^ 1][im],
                          aA + (uint32_t)(im * 16 * STR) * 2 + (ks + 1) * 32);
            }
            // HMMAs in-major: bf[0] group runs while bf[1..3] land
            #pragma unroll
            for (int in = 0; in < 4; in++)
                #pragma unroll
                for (int im = 0; im < 4; im++) {
                    mma16816(acc[im][2 * in],     af[cur][im], &bf[in][0]);
                    mma16816(acc[im][2 * in + 1], af[cur][im], &bf[in][2]);
                }
        }
    }

    // ---- epilogue: direct STG, 32B-sector coalesced -------------------------
    #pragma unroll
    for (int im = 0; im < 4; im++) {
        int o = ot * 128 + m0 + im * 16 + (lane >> 2);
        float* p = out + ((size_t)(b * CHANNELS + o)) * HW
                       + (size_t)pt * 128 + n0 + 2 * (lane & 3);
        #pragma unroll
        for (int inf = 0; inf < 8; inf++) {
            float2 vlo = make_float2(acc[im][inf][0], acc[im][inf][1]);
            float2 vhi = make_float2(acc[im][inf][2], acc[im][inf][3]);
            *(float2*)(p + inf * 8)          = vlo;   // row o
            *(float2*)(p + inf * 8 + 8 * HW) = vhi;   // row o+8
        }
    }
}

// ---------------- launch ------------------------------------------------------
extern "C" void kernel_launch(void* const* d_in, const int* in_sizes, int n_in,
                              void* d_out, int out_size) {
    const float* w        = (const float*)d_in[0];
    const float* affine_w = (const float*)d_in[1];
    const float* affine_b = (const float*)d_in[2];
    const float* freqs    = (const float*)d_in[3];
    const float* phases   = (const float*)d_in[4];
    const float* weight   = (const float*)d_in[5];
    float* out = (float*)d_out;

    cudaFuncSetAttribute(gemm_mma, cudaFuncAttributeMaxDynamicSharedMemorySize,
                         SMEM_BYTES);

    params_kernel<<<BATCH, 128>>>(w, affine_w, affine_b, freqs, phases);
    wconv_kernel<<<512, 256>>>(weight);
    tables_kernel<<<dim3(GRID_HW, BATCH), 256>>>();
    features_kernel<<<dim3(GRID_HW, BATCH), 256>>>();
    gemm_mma<<<dim3(8, 32, BATCH), 128, SMEM_BYTES>>>(out);
}